// round 1
// baseline (speedup 1.0000x reference)
#include <cuda_runtime.h>
#include <cstdint>

// SGConv K=2: h = P (P x), P = D^-1/2 (A + I) D^-1/2, deg over dst + self loop.
// Strategy: build CSR (sorted by dst) once per launch, precompute per-edge
// coefficient, then two gather-based hop kernels (one warp per node, 3 regs/lane).
// Feature table (19.2 MB) is L2-resident -> hops are L2-bandwidth bound, no atomics.

#define N_NODES 50000
#define N_EDGES 800000
#define N_FEAT  96

// ---------------- device scratch (allocation-free rule: __device__ globals) ----
__device__ int   g_is64;                    // 1 if edge_index is int64, 0 if int32
__device__ int   g_counts[N_NODES];         // in-degree (dst)
__device__ int   g_cursor[N_NODES];         // scatter cursors
__device__ int   g_rowptr[N_NODES + 1];     // CSR row pointers (by dst)
__device__ float g_dis[N_NODES];            // deg^-1/2
__device__ int   g_col[N_EDGES];            // src per CSR slot
__device__ float g_coef[N_EDGES];           // dis[src]*dis[dst] per CSR slot
__device__ float g_tmp[(size_t)N_NODES * N_FEAT]; // hop-1 output

// ---------------- dtype detection ---------------------------------------------
// Values are in [0, 50000). If stored as int64 (little-endian), every odd
// 32-bit word is 0. If int32, odd words are ~uniform in [0,50000) -> almost
// surely nonzero among 2048 samples.
__global__ void detect_kernel(const void* ei) {
    __shared__ int nz;
    if (threadIdx.x == 0) nz = 0;
    __syncthreads();
    const int* w = (const int*)ei;
    int local = 0;
    for (int i = threadIdx.x; i < 2048; i += blockDim.x)
        if (w[2 * i + 1] != 0) local = 1;
    if (local) atomicExch(&nz, 1);
    __syncthreads();
    if (threadIdx.x == 0) g_is64 = (nz == 0) ? 1 : 0;
}

__device__ __forceinline__ int edge_src(const void* ei, int e) {
    if (g_is64) return (int)((const long long*)ei)[e];
    return ((const int*)ei)[e];
}
__device__ __forceinline__ int edge_dst(const void* ei, int e) {
    if (g_is64) return (int)((const long long*)ei)[N_EDGES + e];
    return ((const int*)ei)[N_EDGES + e];
}

// ---------------- CSR build ----------------------------------------------------
__global__ void zero_kernel() {
    int i = blockIdx.x * blockDim.x + threadIdx.x;
    if (i < N_NODES) { g_counts[i] = 0; g_cursor[i] = 0; }
}

__global__ void degree_kernel(const void* __restrict__ ei) {
    int e = blockIdx.x * blockDim.x + threadIdx.x;
    if (e < N_EDGES) atomicAdd(&g_counts[edge_dst(ei, e)], 1);
}

__global__ void dis_kernel() {
    int i = blockIdx.x * blockDim.x + threadIdx.x;
    if (i < N_NODES) g_dis[i] = rsqrtf((float)(g_counts[i] + 1)); // +1 self loop
}

// Single-block exclusive prefix sum over g_counts -> g_rowptr. 1024 threads,
// warp shfl scans; 49 chunks.
__global__ void scan_kernel() {
    __shared__ int wsum[32];
    __shared__ int carry;
    const int tid = threadIdx.x, lane = tid & 31, wid = tid >> 5;
    if (tid == 0) { carry = 0; g_rowptr[0] = 0; }
    __syncthreads();
    for (int base = 0; base < N_NODES; base += 1024) {
        int i = base + tid;
        int v = (i < N_NODES) ? g_counts[i] : 0;
        int incl = v;
        #pragma unroll
        for (int off = 1; off < 32; off <<= 1) {
            int t = __shfl_up_sync(0xFFFFFFFFu, incl, off);
            if (lane >= off) incl += t;
        }
        if (lane == 31) wsum[wid] = incl;
        __syncthreads();
        if (wid == 0) {
            int s = wsum[lane];
            #pragma unroll
            for (int off = 1; off < 32; off <<= 1) {
                int t = __shfl_up_sync(0xFFFFFFFFu, s, off);
                if (lane >= off) s += t;
            }
            wsum[lane] = s;
        }
        __syncthreads();
        int offset = carry + (wid > 0 ? wsum[wid - 1] : 0);
        if (i < N_NODES) g_rowptr[i + 1] = offset + incl;
        __syncthreads();
        if (tid == 0) carry += wsum[31];
        __syncthreads();
    }
}

__global__ void scatter_kernel(const void* __restrict__ ei) {
    int e = blockIdx.x * blockDim.x + threadIdx.x;
    if (e >= N_EDGES) return;
    int s = edge_src(ei, e);
    int d = edge_dst(ei, e);
    int pos = g_rowptr[d] + atomicAdd(&g_cursor[d], 1);
    g_col[pos]  = s;
    g_coef[pos] = g_dis[s] * g_dis[d];
}

// ---------------- hop: one warp per node, 3 accumulators per lane --------------
__global__ void __launch_bounds__(256) hop_kernel(const float* __restrict__ hin,
                                                  float* __restrict__ hout) {
    const int node = blockIdx.x * (blockDim.x >> 5) + (threadIdx.x >> 5);
    if (node >= N_NODES) return;
    const int lane = threadIdx.x & 31;

    // self-loop term: dis[node]^2 * h[node]
    float sc = g_dis[node];
    sc = sc * sc;
    const float* hn = hin + (size_t)node * N_FEAT;
    float a0 = sc * hn[lane];
    float a1 = sc * hn[lane + 32];
    float a2 = sc * hn[lane + 64];

    int e   = g_rowptr[node];
    const int end = g_rowptr[node + 1];

    // 2-edge unroll for MLP
    for (; e + 1 < end; e += 2) {
        float c0 = g_coef[e];     int s0 = g_col[e];
        float c1 = g_coef[e + 1]; int s1 = g_col[e + 1];
        const float* h0 = hin + (size_t)s0 * N_FEAT;
        const float* h1 = hin + (size_t)s1 * N_FEAT;
        float x00 = h0[lane], x01 = h0[lane + 32], x02 = h0[lane + 64];
        float x10 = h1[lane], x11 = h1[lane + 32], x12 = h1[lane + 64];
        a0 += c0 * x00; a1 += c0 * x01; a2 += c0 * x02;
        a0 += c1 * x10; a1 += c1 * x11; a2 += c1 * x12;
    }
    if (e < end) {
        float c = g_coef[e]; int s = g_col[e];
        const float* hs = hin + (size_t)s * N_FEAT;
        a0 += c * hs[lane]; a1 += c * hs[lane + 32]; a2 += c * hs[lane + 64];
    }

    float* ho = hout + (size_t)node * N_FEAT;
    ho[lane] = a0; ho[lane + 32] = a1; ho[lane + 64] = a2;
}

// ---------------- launch --------------------------------------------------------
extern "C" void kernel_launch(void* const* d_in, const int* in_sizes, int n_in,
                              void* d_out, int out_size) {
    const float* x  = (const float*)d_in[0];
    const void*  ei = d_in[1];
    float* out = (float*)d_out;

    float* tmp = nullptr;
    cudaGetSymbolAddress((void**)&tmp, g_tmp);

    const int TB = 256;
    detect_kernel<<<1, 256>>>(ei);
    zero_kernel<<<(N_NODES + TB - 1) / TB, TB>>>();
    degree_kernel<<<(N_EDGES + TB - 1) / TB, TB>>>(ei);
    dis_kernel<<<(N_NODES + TB - 1) / TB, TB>>>();
    scan_kernel<<<1, 1024>>>();
    scatter_kernel<<<(N_EDGES + TB - 1) / TB, TB>>>(ei);

    const int warps_per_block = TB / 32;
    const int hop_grid = (N_NODES + warps_per_block - 1) / warps_per_block;
    hop_kernel<<<hop_grid, TB>>>(x, tmp);
    hop_kernel<<<hop_grid, TB>>>(tmp, out);
}